// round 1
// baseline (speedup 1.0000x reference)
#include <cuda_runtime.h>
#include <math.h>

#define NN 50000
#define EE 800000
#define ETOT (NN + EE)

__device__ float g_A[NN * 128];
__device__ float g_B[NN * 128];
__device__ float g_asrc[NN * 4];
__device__ float g_adst[NN * 4];
__device__ int   g_counts[NN];
__device__ int   g_rowptr[NN + 1];
__device__ int   g_cursor[NN];
__device__ int   g_col[ETOT];

// ---------------- CSR build ----------------

__global__ void zero_counts_kernel() {
    int i = blockIdx.x * blockDim.x + threadIdx.x;
    if (i < NN) g_counts[i] = 0;
}

__global__ void count_kernel(const int* __restrict__ ei, int E, int etot) {
    int i = blockIdx.x * blockDim.x + threadIdx.x;
    if (i >= etot) return;
    int dst = (i < E) ? ei[E + i] : (i - E);
    atomicAdd(&g_counts[dst], 1);
}

// single-block exclusive scan: counts -> rowptr
__global__ void scan_kernel(int n) {
    __shared__ int wsum[32];
    __shared__ int carry;
    int tid = threadIdx.x, lane = tid & 31, wid = tid >> 5;
    if (tid == 0) carry = 0;
    __syncthreads();
    for (int base = 0; base < n; base += 1024) {
        int i = base + tid;
        int v = (i < n) ? g_counts[i] : 0;
        int x = v;
        #pragma unroll
        for (int o = 1; o < 32; o <<= 1) {
            int t = __shfl_up_sync(0xffffffffu, x, o);
            if (lane >= o) x += t;
        }
        if (lane == 31) wsum[wid] = x;
        __syncthreads();
        if (wid == 0) {
            int w = wsum[lane];
            #pragma unroll
            for (int o = 1; o < 32; o <<= 1) {
                int t = __shfl_up_sync(0xffffffffu, w, o);
                if (lane >= o) w += t;
            }
            wsum[lane] = w;
        }
        __syncthreads();
        int excl = x - v + (wid > 0 ? wsum[wid - 1] : 0);
        int c = carry;
        if (i < n) g_rowptr[i] = c + excl;
        __syncthreads();
        if (tid == 1023) carry = c + excl + v;
        __syncthreads();
    }
    if (tid == 0) g_rowptr[n] = carry;
}

__global__ void copy_cursor_kernel() {
    int i = blockIdx.x * blockDim.x + threadIdx.x;
    if (i < NN) g_cursor[i] = g_rowptr[i];
}

__global__ void fill_kernel(const int* __restrict__ ei, int E, int etot) {
    int i = blockIdx.x * blockDim.x + threadIdx.x;
    if (i >= etot) return;
    int s, d;
    if (i < E) { s = ei[i]; d = ei[E + i]; }
    else       { s = i - E; d = i - E; }
    int p = atomicAdd(&g_cursor[d], 1);
    g_col[p] = s;
}

// ---------------- Linear + per-node attention logits ----------------
// h = X @ W  ([nrows,K] x [K,COUT]), also asrc[n,h] = sum_c h*a_s, adst likewise.

template <int K, int COUT, int HEADS, int CH, int RT>
__global__ void lin_kernel(const float* __restrict__ X, const float* __restrict__ W,
                           const float* __restrict__ a_s, const float* __restrict__ a_d,
                           float* __restrict__ Hout, float* __restrict__ asrc,
                           float* __restrict__ adst, int nrows, int rpb) {
    extern __shared__ float sm[];
    float* Ws = sm;                 // K*COUT
    float* xs = Ws + K * COUT;      // RT*K
    float* rs = xs + RT * K;        // RT*COUT
    float* rd = rs + RT * COUT;     // RT*COUT
    int tid = threadIdx.x;
    for (int i = tid; i < K * COUT; i += blockDim.x) Ws[i] = W[i];

    int row0 = blockIdx.x * rpb;
    int rowE = min(row0 + rpb, nrows);
    for (int r0 = row0; r0 < rowE; r0 += RT) {
        int nr = min(RT, rowE - r0);
        __syncthreads();
        for (int i = tid; i < nr * K; i += blockDim.x) xs[i] = X[r0 * K + i];
        __syncthreads();
        if (tid < COUT) {
            float acc[RT];
            #pragma unroll
            for (int r = 0; r < RT; r++) acc[r] = 0.f;
            #pragma unroll 4
            for (int k = 0; k < K; k++) {
                float w = Ws[k * COUT + tid];
                #pragma unroll
                for (int r = 0; r < RT; r++) acc[r] += xs[r * K + k] * w;
            }
            float va = a_s[tid], vd = a_d[tid];
            #pragma unroll
            for (int r = 0; r < RT; r++) {
                if (r < nr) {
                    Hout[(r0 + r) * COUT + tid] = acc[r];
                    rs[r * COUT + tid] = acc[r] * va;
                    rd[r * COUT + tid] = acc[r] * vd;
                }
            }
        }
        __syncthreads();
        if (tid < RT * HEADS) {
            int r = tid / HEADS, hd = tid % HEADS;
            if (r < nr) {
                float ss = 0.f, sd = 0.f;
                #pragma unroll 4
                for (int c = 0; c < CH; c++) {
                    ss += rs[r * COUT + hd * CH + c];
                    sd += rd[r * COUT + hd * CH + c];
                }
                asrc[(r0 + r) * HEADS + hd] = ss;
                adst[(r0 + r) * HEADS + hd] = sd;
            }
        }
    }
}

// ---------------- Aggregation (layers 0/1): HEADS=4, CH=32 ----------------
// one warp per (node, head); lane = channel; online softmax.

__global__ void agg_kernel(const float* __restrict__ Hin, const float* __restrict__ asrc,
                           const float* __restrict__ adst, const float* __restrict__ bias,
                           float* __restrict__ Hout) {
    int wg = (blockIdx.x * blockDim.x + threadIdx.x) >> 5;
    if (wg >= NN * 4) return;
    int node = wg >> 2, head = wg & 3;
    int lane = threadIdx.x & 31;
    int s = g_rowptr[node], e = g_rowptr[node + 1];
    float ad = adst[node * 4 + head];
    float m = -INFINITY, ssum = 0.f, acc = 0.f;
    for (int i = s; i < e; i++) {
        int src = g_col[i];
        float lg = asrc[src * 4 + head] + ad;
        lg = lg > 0.f ? lg : 0.2f * lg;
        float mn = fmaxf(m, lg);
        float sc = __expf(m - mn);
        float ce = __expf(lg - mn);
        ssum = ssum * sc + ce;
        acc = acc * sc + ce * Hin[src * 128 + head * 32 + lane];
        m = mn;
    }
    float out = acc / (ssum + 1e-16f) + bias[head * 32 + lane];
    out = out > 0.f ? out : expm1f(out);   // ELU
    Hout[node * 128 + head * 32 + lane] = out;
}

// ---------------- Aggregation layer 2: 1 head, 40 ch, + log_softmax ----------------

__global__ void agg2_kernel(const float* __restrict__ Hin, const float* __restrict__ asrc,
                            const float* __restrict__ adst, const float* __restrict__ bias,
                            float* __restrict__ out) {
    int wg = (blockIdx.x * blockDim.x + threadIdx.x) >> 5;
    if (wg >= NN) return;
    int node = wg;
    int lane = threadIdx.x & 31;
    int s = g_rowptr[node], e = g_rowptr[node + 1];
    float ad = adst[node];
    float m = -INFINITY, ssum = 0.f, acc0 = 0.f, acc1 = 0.f;
    for (int i = s; i < e; i++) {
        int src = g_col[i];
        float lg = asrc[src] + ad;
        lg = lg > 0.f ? lg : 0.2f * lg;
        float mn = fmaxf(m, lg);
        float sc = __expf(m - mn);
        float ce = __expf(lg - mn);
        ssum = ssum * sc + ce;
        acc0 = acc0 * sc + ce * Hin[src * 40 + lane];
        if (lane < 8) acc1 = acc1 * sc + ce * Hin[src * 40 + 32 + lane];
        m = mn;
    }
    float inv = 1.f / (ssum + 1e-16f);
    float v0 = acc0 * inv + bias[lane];
    float v1 = (lane < 8) ? (acc1 * inv + bias[32 + lane]) : -INFINITY;
    // log_softmax over 40 classes within the warp
    float mx = fmaxf(v0, v1);
    #pragma unroll
    for (int o = 16; o > 0; o >>= 1) mx = fmaxf(mx, __shfl_xor_sync(0xffffffffu, mx, o));
    float se = __expf(v0 - mx) + ((lane < 8) ? __expf(v1 - mx) : 0.f);
    #pragma unroll
    for (int o = 16; o > 0; o >>= 1) se += __shfl_xor_sync(0xffffffffu, se, o);
    float lse = mx + logf(se);
    out[node * 40 + lane] = v0 - lse;
    if (lane < 8) out[node * 40 + 32 + lane] = v1 - lse;
}

// ---------------- host ----------------

extern "C" void kernel_launch(void* const* d_in, const int* in_sizes, int n_in,
                              void* d_out, int out_size) {
    const float* x   = (const float*)d_in[0];
    const int*   ei  = (const int*)d_in[1];
    const float* W0  = (const float*)d_in[2];
    const float* as0 = (const float*)d_in[3];
    const float* ad0 = (const float*)d_in[4];
    const float* b0  = (const float*)d_in[5];
    const float* W1  = (const float*)d_in[6];
    const float* as1 = (const float*)d_in[7];
    const float* ad1 = (const float*)d_in[8];
    const float* b1  = (const float*)d_in[9];
    const float* W2  = (const float*)d_in[10];
    const float* as2 = (const float*)d_in[11];
    const float* ad2 = (const float*)d_in[12];
    const float* b2  = (const float*)d_in[13];
    float* out = (float*)d_out;

    int E = in_sizes[1] / 2;
    int etot = E + NN;

    float *A, *B, *asrc, *adst;
    cudaGetSymbolAddress((void**)&A, g_A);
    cudaGetSymbolAddress((void**)&B, g_B);
    cudaGetSymbolAddress((void**)&asrc, g_asrc);
    cudaGetSymbolAddress((void**)&adst, g_adst);

    // CSR build
    zero_counts_kernel<<<(NN + 255) / 256, 256>>>();
    count_kernel<<<(etot + 255) / 256, 256>>>(ei, E, etot);
    scan_kernel<<<1, 1024>>>(NN);
    copy_cursor_kernel<<<(NN + 255) / 256, 256>>>();
    fill_kernel<<<(etot + 255) / 256, 256>>>(ei, E, etot);

    // shared-mem sizes
    const int smem_l01 = (128 * 128 + 4 * 128 + 2 * 4 * 128) * 4;  // 71680
    const int smem_l2  = (128 * 40 + 4 * 128 + 2 * 4 * 40) * 4;
    cudaFuncSetAttribute(lin_kernel<128, 128, 4, 32, 4>,
                         cudaFuncAttributeMaxDynamicSharedMemorySize, smem_l01);
    cudaFuncSetAttribute(lin_kernel<128, 40, 1, 40, 4>,
                         cudaFuncAttributeMaxDynamicSharedMemorySize, smem_l2);

    const int RPB = 64;
    int lin_grid = (NN + RPB - 1) / RPB;
    int agg_grid  = (NN * 4 * 32 + 255) / 256;  // warp per (node,head)
    int agg2_grid = (NN * 32 + 255) / 256;      // warp per node

    // layer 0
    lin_kernel<128, 128, 4, 32, 4><<<lin_grid, 128, smem_l01>>>(x, W0, as0, ad0, A, asrc, adst, NN, RPB);
    agg_kernel<<<agg_grid, 256>>>(A, asrc, adst, b0, B);
    // layer 1
    lin_kernel<128, 128, 4, 32, 4><<<lin_grid, 128, smem_l01>>>(B, W1, as1, ad1, A, asrc, adst, NN, RPB);
    agg_kernel<<<agg_grid, 256>>>(A, asrc, adst, b1, B);
    // layer 2
    lin_kernel<128, 40, 1, 40, 4><<<lin_grid, 128, smem_l2>>>(B, W2, as2, ad2, A, asrc, adst, NN, RPB);
    agg2_kernel<<<agg2_grid, 256>>>(A, asrc, adst, b2, out);

    (void)n_in; (void)out_size;
}

// round 2
// speedup vs baseline: 2.1543x; 2.1543x over previous
#include <cuda_runtime.h>
#include <math.h>

#define NN 50000
#define EE 800000
#define ETOT (NN + EE)

typedef unsigned long long ull;

__device__ float g_A[NN * 128];
__device__ float g_B[NN * 128];
__device__ float g_asrc[NN * 4];
__device__ float g_adst[NN * 4];
__device__ int   g_counts[NN];
__device__ int   g_rowptr[NN + 1];
__device__ int   g_cursor[NN];
__device__ int   g_col[ETOT];
__device__ int   g_part[256];
__device__ int   g_part_scan[256];

// ---------------- packed f32x2 helpers ----------------

__device__ __forceinline__ ull pack2(float x) {
    ull r;
    asm("mov.b64 %0, {%1, %1};" : "=l"(r) : "f"(x));
    return r;
}
__device__ __forceinline__ void ffma2(ull& d, ull a, ull b) {
    asm("fma.rn.f32x2 %0, %1, %2, %0;" : "+l"(d) : "l"(a), "l"(b));
}
__device__ __forceinline__ float2 unpack2(ull v) {
    float2 f;
    asm("mov.b64 {%0, %1}, %2;" : "=f"(f.x), "=f"(f.y) : "l"(v));
    return f;
}

// ---------------- CSR build ----------------

__global__ void zero_counts_kernel() {
    int i = blockIdx.x * blockDim.x + threadIdx.x;
    if (i < NN) g_counts[i] = 0;
}

__global__ void count_kernel(const int* __restrict__ ei, int E, int etot) {
    int i = blockIdx.x * blockDim.x + threadIdx.x;
    if (i >= etot) return;
    int dst = (i < E) ? ei[E + i] : (i - E);
    atomicAdd(&g_counts[dst], 1);
}

__device__ __forceinline__ int block_excl_scan(int v, int tid) {
    __shared__ int ws[8];
    int lane = tid & 31, wid = tid >> 5;
    int x = v;
    #pragma unroll
    for (int o = 1; o < 32; o <<= 1) {
        int t = __shfl_up_sync(0xffffffffu, x, o);
        if (lane >= o) x += t;
    }
    if (lane == 31) ws[wid] = x;
    __syncthreads();
    if (wid == 0) {
        int w = (lane < 8) ? ws[lane] : 0;
        #pragma unroll
        for (int o = 1; o < 8; o <<= 1) {
            int t = __shfl_up_sync(0xffffffffu, w, o);
            if (lane >= o) w += t;
        }
        if (lane < 8) ws[lane] = w;
    }
    __syncthreads();
    return x - v + (wid ? ws[wid - 1] : 0);
}

__global__ void reduce_kernel() {   // per-block sums of counts
    int tid = threadIdx.x;
    int i = blockIdx.x * 256 + tid;
    int v = (i < NN) ? g_counts[i] : 0;
    #pragma unroll
    for (int o = 16; o > 0; o >>= 1) v += __shfl_down_sync(0xffffffffu, v, o);
    __shared__ int ws[8];
    if ((tid & 31) == 0) ws[tid >> 5] = v;
    __syncthreads();
    if (tid == 0) {
        int s = 0;
        #pragma unroll
        for (int w = 0; w < 8; w++) s += ws[w];
        g_part[blockIdx.x] = s;
    }
}

__global__ void scanp_kernel(int nb) {  // scan the 196 partials, 1 block
    int tid = threadIdx.x;
    int v = (tid < nb) ? g_part[tid] : 0;
    int e = block_excl_scan(v, tid);
    if (tid < nb) g_part_scan[tid] = e;
}

__global__ void scanf_kernel(int etot) {  // final rowptr + cursor
    int tid = threadIdx.x;
    int i = blockIdx.x * 256 + tid;
    int v = (i < NN) ? g_counts[i] : 0;
    int e = block_excl_scan(v, tid) + g_part_scan[blockIdx.x];
    if (i < NN) { g_rowptr[i] = e; g_cursor[i] = e; }
    if (i == 0) g_rowptr[NN] = etot;
}

__global__ void fill_kernel(const int* __restrict__ ei, int E, int etot) {
    int i = blockIdx.x * blockDim.x + threadIdx.x;
    if (i >= etot) return;
    int s, d;
    if (i < E) { s = ei[i]; d = ei[E + i]; }
    else       { s = i - E; d = i - E; }
    int p = atomicAdd(&g_cursor[d], 1);
    g_col[p] = s;
}

// ---------------- Fast 128x128 linear (layers 0/1) ----------------
// Block: 256 threads, tile 64 rows x 128 cols. Thread: 8 rows x 4 cols,
// accumulated as 4 row-pairs x 4 cols in packed f32x2.

__global__ void lin128_kernel(const float* __restrict__ X, const float* __restrict__ W,
                              const float* __restrict__ a_s, const float* __restrict__ a_d,
                              float* __restrict__ Hout, float* __restrict__ asrc,
                              float* __restrict__ adst, int nrows) {
    extern __shared__ float sm[];
    float* Ws = sm;              // [128][128]
    float* Xt = sm + 128 * 128;  // [128][66] transposed (k-major, m contiguous)
    int tid = threadIdx.x;
    int row0 = blockIdx.x * 64;

    {
        const float4* Wg = (const float4*)W;
        float4* Wsh = (float4*)Ws;
        for (int i = tid; i < 128 * 32; i += 256) Wsh[i] = Wg[i];
    }
    for (int i = tid; i < 64 * 128; i += 256) {
        int m = i >> 7, k = i & 127;
        float v = (row0 + m < nrows) ? X[(row0 + m) * 128 + k] : 0.f;
        Xt[k * 66 + m] = v;
    }
    __syncthreads();

    int tn = tid & 31, tm = tid >> 5;
    int n0 = tn * 4, m0 = tm * 8;

    ull acc[4][4];
    #pragma unroll
    for (int p = 0; p < 4; p++)
        #pragma unroll
        for (int j = 0; j < 4; j++) acc[p][j] = 0ULL;

    const float* wp = Ws + n0;
    const float* xp = Xt + m0;
    #pragma unroll 4
    for (int k = 0; k < 128; k++) {
        float4 bv = *(const float4*)(wp + k * 128);
        ull b0 = pack2(bv.x), b1 = pack2(bv.y), b2 = pack2(bv.z), b3 = pack2(bv.w);
        const ull* ap = (const ull*)(xp + k * 66);
        ull a0 = ap[0], a1 = ap[1], a2 = ap[2], a3 = ap[3];
        ffma2(acc[0][0], a0, b0); ffma2(acc[0][1], a0, b1);
        ffma2(acc[0][2], a0, b2); ffma2(acc[0][3], a0, b3);
        ffma2(acc[1][0], a1, b0); ffma2(acc[1][1], a1, b1);
        ffma2(acc[1][2], a1, b2); ffma2(acc[1][3], a1, b3);
        ffma2(acc[2][0], a2, b0); ffma2(acc[2][1], a2, b1);
        ffma2(acc[2][2], a2, b2); ffma2(acc[2][3], a2, b3);
        ffma2(acc[3][0], a3, b0); ffma2(acc[3][1], a3, b1);
        ffma2(acc[3][2], a3, b2); ffma2(acc[3][3], a3, b3);
    }

    float va0 = a_s[n0], va1 = a_s[n0 + 1], va2 = a_s[n0 + 2], va3 = a_s[n0 + 3];
    float vd0 = a_d[n0], vd1 = a_d[n0 + 1], vd2 = a_d[n0 + 2], vd3 = a_d[n0 + 3];
    int head = tn >> 3;

    #pragma unroll
    for (int p = 0; p < 4; p++) {
        float2 f0 = unpack2(acc[p][0]), f1 = unpack2(acc[p][1]);
        float2 f2 = unpack2(acc[p][2]), f3 = unpack2(acc[p][3]);
        #pragma unroll
        for (int h = 0; h < 2; h++) {
            int row = row0 + m0 + 2 * p + h;
            float v0 = h ? f0.y : f0.x;
            float v1 = h ? f1.y : f1.x;
            float v2 = h ? f2.y : f2.x;
            float v3 = h ? f3.y : f3.x;
            bool valid = (row < nrows);
            if (valid) {
                float4 o = make_float4(v0, v1, v2, v3);
                *(float4*)(Hout + row * 128 + n0) = o;
            }
            float ss = v0 * va0 + v1 * va1 + v2 * va2 + v3 * va3;
            float sd = v0 * vd0 + v1 * vd1 + v2 * vd2 + v3 * vd3;
            #pragma unroll
            for (int o = 1; o < 8; o <<= 1) {
                ss += __shfl_xor_sync(0xffffffffu, ss, o);
                sd += __shfl_xor_sync(0xffffffffu, sd, o);
            }
            if (valid && (tn & 7) == 0) {
                asrc[row * 4 + head] = ss;
                adst[row * 4 + head] = sd;
            }
        }
    }
}

// ---------------- Linear layer 2 (K=128, COUT=40) ----------------

template <int K, int COUT, int HEADS, int CH, int RT>
__global__ void lin_kernel(const float* __restrict__ X, const float* __restrict__ W,
                           const float* __restrict__ a_s, const float* __restrict__ a_d,
                           float* __restrict__ Hout, float* __restrict__ asrc,
                           float* __restrict__ adst, int nrows, int rpb) {
    extern __shared__ float sm[];
    float* Ws = sm;
    float* xs = Ws + K * COUT;
    float* rs = xs + RT * K;
    float* rd = rs + RT * COUT;
    int tid = threadIdx.x;
    for (int i = tid; i < K * COUT; i += blockDim.x) Ws[i] = W[i];

    int row0 = blockIdx.x * rpb;
    int rowE = min(row0 + rpb, nrows);
    for (int r0 = row0; r0 < rowE; r0 += RT) {
        int nr = min(RT, rowE - r0);
        __syncthreads();
        for (int i = tid; i < nr * K; i += blockDim.x) xs[i] = X[r0 * K + i];
        __syncthreads();
        if (tid < COUT) {
            float acc[RT];
            #pragma unroll
            for (int r = 0; r < RT; r++) acc[r] = 0.f;
            #pragma unroll 4
            for (int k = 0; k < K; k++) {
                float w = Ws[k * COUT + tid];
                #pragma unroll
                for (int r = 0; r < RT; r++) acc[r] += xs[r * K + k] * w;
            }
            float va = a_s[tid], vd = a_d[tid];
            #pragma unroll
            for (int r = 0; r < RT; r++) {
                if (r < nr) {
                    Hout[(r0 + r) * COUT + tid] = acc[r];
                    rs[r * COUT + tid] = acc[r] * va;
                    rd[r * COUT + tid] = acc[r] * vd;
                }
            }
        }
        __syncthreads();
        if (tid < RT * HEADS) {
            int r = tid / HEADS, hd = tid % HEADS;
            if (r < nr) {
                float ss = 0.f, sd = 0.f;
                #pragma unroll 4
                for (int c = 0; c < CH; c++) {
                    ss += rs[r * COUT + hd * CH + c];
                    sd += rd[r * COUT + hd * CH + c];
                }
                asrc[(r0 + r) * HEADS + hd] = ss;
                adst[(r0 + r) * HEADS + hd] = sd;
            }
        }
    }
}

// ---------------- Aggregation layers 0/1: one warp per node, 4 heads ----------------
// lane l: head = l>>3, channels l*4 .. l*4+3 (= head*32 + (l&7)*4 ..)

__global__ void agg_kernel(const float* __restrict__ Hin, const float* __restrict__ asrc,
                           const float* __restrict__ adst, const float* __restrict__ bias,
                           float* __restrict__ Hout) {
    int node = (blockIdx.x * blockDim.x + threadIdx.x) >> 5;
    if (node >= NN) return;
    int lane = threadIdx.x & 31;
    int head = lane >> 3;
    int s = g_rowptr[node], e = g_rowptr[node + 1];
    float ad = adst[node * 4 + head];
    float m = -INFINITY, ssum = 0.f;
    float a0 = 0.f, a1 = 0.f, a2 = 0.f, a3 = 0.f;
    for (int i = s; i < e; i++) {
        int src = g_col[i];
        float lg = asrc[src * 4 + head] + ad;
        lg = fmaxf(lg, 0.2f * lg);  // leaky_relu
        float mn = fmaxf(m, lg);
        float sc = __expf(m - mn);
        float ce = __expf(lg - mn);
        float4 h = *(const float4*)(Hin + src * 128 + lane * 4);
        ssum = ssum * sc + ce;
        a0 = a0 * sc + ce * h.x;
        a1 = a1 * sc + ce * h.y;
        a2 = a2 * sc + ce * h.z;
        a3 = a3 * sc + ce * h.w;
        m = mn;
    }
    float inv = 1.f / (ssum + 1e-16f);
    float4 b4 = *(const float4*)(bias + lane * 4);
    float o0 = a0 * inv + b4.x;
    float o1 = a1 * inv + b4.y;
    float o2 = a2 * inv + b4.z;
    float o3 = a3 * inv + b4.w;
    o0 = o0 > 0.f ? o0 : expm1f(o0);
    o1 = o1 > 0.f ? o1 : expm1f(o1);
    o2 = o2 > 0.f ? o2 : expm1f(o2);
    o3 = o3 > 0.f ? o3 : expm1f(o3);
    *(float4*)(Hout + node * 128 + lane * 4) = make_float4(o0, o1, o2, o3);
}

// ---------------- Aggregation layer 2: 1 head, 40 ch, + log_softmax ----------------

__global__ void agg2_kernel(const float* __restrict__ Hin, const float* __restrict__ asrc,
                            const float* __restrict__ adst, const float* __restrict__ bias,
                            float* __restrict__ out) {
    int node = (blockIdx.x * blockDim.x + threadIdx.x) >> 5;
    if (node >= NN) return;
    int lane = threadIdx.x & 31;
    int s = g_rowptr[node], e = g_rowptr[node + 1];
    float ad = adst[node];
    float m = -INFINITY, ssum = 0.f, acc0 = 0.f, acc1 = 0.f;
    for (int i = s; i < e; i++) {
        int src = g_col[i];
        float lg = asrc[src] + ad;
        lg = fmaxf(lg, 0.2f * lg);
        float mn = fmaxf(m, lg);
        float sc = __expf(m - mn);
        float ce = __expf(lg - mn);
        ssum = ssum * sc + ce;
        acc0 = acc0 * sc + ce * Hin[src * 40 + lane];
        if (lane < 8) acc1 = acc1 * sc + ce * Hin[src * 40 + 32 + lane];
        m = mn;
    }
    float inv = 1.f / (ssum + 1e-16f);
    float v0 = acc0 * inv + bias[lane];
    float v1 = (lane < 8) ? (acc1 * inv + bias[32 + lane]) : -INFINITY;
    float mx = fmaxf(v0, v1);
    #pragma unroll
    for (int o = 16; o > 0; o >>= 1) mx = fmaxf(mx, __shfl_xor_sync(0xffffffffu, mx, o));
    float se = __expf(v0 - mx) + ((lane < 8) ? __expf(v1 - mx) : 0.f);
    #pragma unroll
    for (int o = 16; o > 0; o >>= 1) se += __shfl_xor_sync(0xffffffffu, se, o);
    float lse = mx + logf(se);
    out[node * 40 + lane] = v0 - lse;
    if (lane < 8) out[node * 40 + 32 + lane] = v1 - lse;
}

// ---------------- host ----------------

extern "C" void kernel_launch(void* const* d_in, const int* in_sizes, int n_in,
                              void* d_out, int out_size) {
    const float* x   = (const float*)d_in[0];
    const int*   ei  = (const int*)d_in[1];
    const float* W0  = (const float*)d_in[2];
    const float* as0 = (const float*)d_in[3];
    const float* ad0 = (const float*)d_in[4];
    const float* b0  = (const float*)d_in[5];
    const float* W1  = (const float*)d_in[6];
    const float* as1 = (const float*)d_in[7];
    const float* ad1 = (const float*)d_in[8];
    const float* b1  = (const float*)d_in[9];
    const float* W2  = (const float*)d_in[10];
    const float* as2 = (const float*)d_in[11];
    const float* ad2 = (const float*)d_in[12];
    const float* b2  = (const float*)d_in[13];
    float* out = (float*)d_out;

    int E = in_sizes[1] / 2;
    int etot = E + NN;

    float *A, *B, *asrc, *adst;
    cudaGetSymbolAddress((void**)&A, g_A);
    cudaGetSymbolAddress((void**)&B, g_B);
    cudaGetSymbolAddress((void**)&asrc, g_asrc);
    cudaGetSymbolAddress((void**)&adst, g_adst);

    const int NB = (NN + 255) / 256;  // 196

    // CSR build
    zero_counts_kernel<<<NB, 256>>>();
    count_kernel<<<(etot + 255) / 256, 256>>>(ei, E, etot);
    reduce_kernel<<<NB, 256>>>();
    scanp_kernel<<<1, 256>>>(NB);
    scanf_kernel<<<NB, 256>>>(etot);
    fill_kernel<<<(etot + 255) / 256, 256>>>(ei, E, etot);

    const int smem_lin128 = (128 * 128 + 128 * 66) * 4;  // 99328
    const int smem_l2 = (128 * 40 + 4 * 128 + 2 * 4 * 40) * 4;
    static bool attr_set = false;
    cudaFuncSetAttribute(lin128_kernel, cudaFuncAttributeMaxDynamicSharedMemorySize, smem_lin128);
    cudaFuncSetAttribute(lin_kernel<128, 40, 1, 40, 4>,
                         cudaFuncAttributeMaxDynamicSharedMemorySize, smem_l2);
    (void)attr_set;

    int lin128_grid = (NN + 63) / 64;            // 782
    int agg_grid = (NN * 32 + 255) / 256;        // warp per node
    const int RPB = 64;
    int lin2_grid = (NN + RPB - 1) / RPB;

    // layer 0
    lin128_kernel<<<lin128_grid, 256, smem_lin128>>>(x, W0, as0, ad0, A, asrc, adst, NN);
    agg_kernel<<<agg_grid, 256>>>(A, asrc, adst, b0, B);
    // layer 1
    lin128_kernel<<<lin128_grid, 256, smem_lin128>>>(B, W1, as1, ad1, A, asrc, adst, NN);
    agg_kernel<<<agg_grid, 256>>>(A, asrc, adst, b1, B);
    // layer 2
    lin_kernel<128, 40, 1, 40, 4><<<lin2_grid, 128, smem_l2>>>(B, W2, as2, ad2, A, asrc, adst, NN, RPB);
    agg2_kernel<<<agg_grid, 256>>>(A, asrc, adst, b2, out);

    (void)n_in; (void)out_size;
}